// round 9
// baseline (speedup 1.0000x reference)
#include <cuda_runtime.h>
#include <cuda_fp16.h>
#include <cstdint>

// ============================================================================
// shift_Windows == 4 batched GEMMs:  Out[o,p] = sum_k W[o,k] * X[k,p] + bias[o]
//   per (b in {0,1}, g in {0,1}):  M(o)=1024, N(p)=13824, K=1024
//   X[k=s'*32+c', p] = x[b, c', t', p],  t' = (g*32 + s' - 16) & 63
//   Out row o=s*32+c  -> out[b, c, t, p], t = (g*32 + s - 16) & 63  (same map)
//
// Baseline compute_103 target: mma.sync.m16n8k16 + cp.async + ldmatrix.
// R8 = R6 fused-conversion design with the A-stage race FIXED:
//   A (W fp16 via cp.async) now has 3 stages (prefetch distance 2 => stage
//   (kc+2)%3 never aliases the stage being read). B (X) is read fp32 directly
//   from the input via LDG.128, converted in registers, stored fp16 to smem
//   (2 buffers, write buf^1 / read buf). xconv prepass eliminated.
// ============================================================================

#define HP3        13824     // 24^3 spatial positions per (b, t)
#define CH_STRIDE  884736    // 64*13824  (channel stride in x/out, elements)
#define B_STRIDE   28311552  // 32*884736 (batch stride, elements)

#define M_TILE 128           // o rows per CTA
#define N_TILE 128           // p cols per CTA
#define N_CHUNKS 16          // 1024 / 64

#define OFF_A 0              // A = W tile: [128 o][64 k] fp16, 128B rows, x3 stages
#define OFF_B 49152          // B = X tile: [64 k][128 p] fp16, 256B rows, x2 buffers
#define SMEM_BYTES 81920     // 48KB A + 32KB B

__device__ __half d_Wh[1024 * 1024];      // fp16 W (prepass)

// ---------------- helpers ----------------
__device__ __forceinline__ uint32_t smem_to_u32(const void* p) {
    uint32_t a;
    asm("{ .reg .u64 t; cvta.to.shared.u64 t, %1; cvt.u32.u64 %0, t; }"
        : "=r"(a) : "l"(p));
    return a;
}
#define CP_ASYNC16(dst, src) \
    asm volatile("cp.async.cg.shared.global [%0], [%1], 16;" :: "r"(dst), "l"(src))
#define CP_COMMIT() asm volatile("cp.async.commit_group;" ::: "memory")
#define CP_WAIT(n)  asm volatile("cp.async.wait_group %0;" :: "n"(n) : "memory")

#define LDMATRIX_X4(r0, r1, r2, r3, addr) \
    asm volatile("ldmatrix.sync.aligned.m8n8.x4.shared.b16 {%0,%1,%2,%3}, [%4];" \
                 : "=r"(r0), "=r"(r1), "=r"(r2), "=r"(r3) : "r"(addr))
#define LDMATRIX_X4_T(r0, r1, r2, r3, addr) \
    asm volatile("ldmatrix.sync.aligned.m8n8.x4.trans.shared.b16 {%0,%1,%2,%3}, [%4];" \
                 : "=r"(r0), "=r"(r1), "=r"(r2), "=r"(r3) : "r"(addr))

#define MMA16816(d, a0, a1, a2, a3, b0, b1) \
    asm volatile("mma.sync.aligned.m16n8k16.row.col.f32.f16.f16.f32 " \
                 "{%0,%1,%2,%3}, {%4,%5,%6,%7}, {%8,%9}, {%0,%1,%2,%3};" \
                 : "+f"((d)[0]), "+f"((d)[1]), "+f"((d)[2]), "+f"((d)[3]) \
                 : "r"(a0), "r"(a1), "r"(a2), "r"(a3), "r"(b0), "r"(b1))

// ---------------- prepass: W fp32 -> fp16 ----------------
__global__ void __launch_bounds__(256) wconv_kernel(const float* __restrict__ W) {
    int i = blockIdx.x * 256 + threadIdx.x;        // 262144 float4's
    float4 v = ((const float4*)W)[i];
    __half2 a = __float22half2_rn(make_float2(v.x, v.y));
    __half2 c = __float22half2_rn(make_float2(v.z, v.w));
    uint2 u;
    u.x = *reinterpret_cast<const uint32_t*>(&a);
    u.y = *reinterpret_cast<const uint32_t*>(&c);
    ((uint2*)d_Wh)[i] = u;
}

// ---------------- main GEMM ----------------
__global__ void __launch_bounds__(256, 1)
swin_gemm_kernel(const float* __restrict__ x, const float* __restrict__ bias,
                 float* __restrict__ out) {
    extern __shared__ char sm[];
    const uint32_t smb = smem_to_u32(sm);
    const int tid  = threadIdx.x;
    const int lane = tid & 31;
    const int warp = tid >> 5;          // 0..7
    const int warp_m = warp & 3;        // o sub-tile (32 rows)
    const int warp_n = warp >> 2;       // p sub-tile (64 cols)

    const int o_base = blockIdx.x * M_TILE;
    const int p_base = blockIdx.y * N_TILE;
    const int bg = blockIdx.z;
    const int b  = bg >> 1;
    const int g  = bg & 1;

    float acc[2][8][4];
    #pragma unroll
    for (int mi = 0; mi < 2; mi++)
        #pragma unroll
        for (int ni = 0; ni < 8; ni++)
            #pragma unroll
            for (int r = 0; r < 4; r++) acc[mi][ni][r] = 0.f;

    // ---- A loader: W fp16 via cp.async, 3 stages (1024 x 16B chunks/stage)
    auto load_A = [&](int stage, int kc) {
        uint32_t abase = smb + OFF_A + stage * 16384;
        #pragma unroll
        for (int i = 0; i < 4; i++) {
            int cid = tid + i * 256;
            int o = cid >> 3, c16 = cid & 7;
            const __half* src = d_Wh + (size_t)(o_base + o) * 1024 + kc * 64 + c16 * 8;
            uint32_t dst = abase + o * 128 + ((c16 * 16) ^ ((o & 7) << 4));
            CP_ASYNC16(dst, src);
        }
    };

    // ---- B: X fp32 gathered by LDG.128 into regs (8 float4 / thread / chunk)
    //      thread cid = tid + i*256 (i<8): kk = cid>>5 (k row), c4 = cid&31
    const float* xb = x + (size_t)b * B_STRIDE + p_base;
    float4 breg[8];

    auto ldg_B = [&](int kc) {
        #pragma unroll
        for (int i = 0; i < 8; i++) {
            int cid = tid + i * 256;
            int kk = cid >> 5, c4 = cid & 31;
            int kg = kc * 64 + kk;
            int sp = kg >> 5, cp = kg & 31;
            int tp = ((g << 5) + sp - 16) & 63;
            breg[i] = *reinterpret_cast<const float4*>(
                xb + (size_t)cp * CH_STRIDE + (size_t)tp * HP3 + c4 * 4);
        }
    };
    // ---- convert regs -> fp16 smem buffer (swizzled to match ldmatrix reads)
    auto cvt_B = [&](int buf) {
        char* bbase = sm + OFF_B + buf * 16384;
        #pragma unroll
        for (int i = 0; i < 8; i++) {
            int cid = tid + i * 256;
            int kk = cid >> 5, c4 = cid & 31;
            float4 v = breg[i];
            __half2 h0 = __float22half2_rn(make_float2(v.x, v.y));
            __half2 h1 = __float22half2_rn(make_float2(v.z, v.w));
            uint2 u;
            u.x = *reinterpret_cast<const uint32_t*>(&h0);
            u.y = *reinterpret_cast<const uint32_t*>(&h1);
            uint32_t off = kk * 256 + ((((c4 >> 1) << 4) ^ ((kk & 7) << 4)))
                         + ((c4 & 1) << 3);
            *reinterpret_cast<uint2*>(bbase + off) = u;
        }
    };

    // ---- prologue: pipeline 2 chunks deep
    ldg_B(0);
    load_A(0, 0); CP_COMMIT();
    cvt_B(0);
    ldg_B(1);
    load_A(1, 1); CP_COMMIT();

    #pragma unroll 1
    for (int kc = 0; kc < N_CHUNKS; kc++) {
        const int buf = kc & 1;          // B read buffer
        const int astage = kc % 3;       // A read stage
        if (kc < N_CHUNKS - 1) { CP_WAIT(1); } else { CP_WAIT(0); }
        __syncthreads();   // A[kc] visible; B fp16 buf[kc] stores (prev iter) visible

        // convert next chunk into the other B buffer; prefetch chunk kc+2
        if (kc + 1 < N_CHUNKS) cvt_B(buf ^ 1);
        if (kc + 2 < N_CHUNKS) {
            ldg_B(kc + 2);
            load_A((kc + 2) % 3, kc + 2); CP_COMMIT();   // distinct stage: no alias
        }

        const uint32_t abase = smb + OFF_A + astage * 16384;
        const uint32_t bbase = smb + OFF_B + buf * 16384;
        #pragma unroll
        for (int k16 = 0; k16 < 4; k16++) {
            uint32_t a[2][4], bb[4][4];
            #pragma unroll
            for (int mi = 0; mi < 2; mi++) {
                int row = warp_m * 32 + mi * 16 + (lane & 15);
                int col = k16 * 32 + (lane >> 4) * 16;
                uint32_t addr = abase + row * 128 + (col ^ ((row & 7) << 4));
                LDMATRIX_X4(a[mi][0], a[mi][1], a[mi][2], a[mi][3], addr);
            }
            #pragma unroll
            for (int ni = 0; ni < 4; ni++) {
                int row = k16 * 16 + (lane & 15);
                int col = warp_n * 128 + ni * 32 + (lane >> 4) * 16;   // bytes
                uint32_t addr = bbase + row * 256 + (col ^ ((row & 7) << 4));
                LDMATRIX_X4_T(bb[ni][0], bb[ni][1], bb[ni][2], bb[ni][3], addr);
            }
            #pragma unroll
            for (int mi = 0; mi < 2; mi++)
                #pragma unroll
                for (int ni = 0; ni < 4; ni++) {
                    MMA16816(acc[mi][2 * ni],     a[mi][0], a[mi][1], a[mi][2], a[mi][3],
                             bb[ni][0], bb[ni][1]);
                    MMA16816(acc[mi][2 * ni + 1], a[mi][0], a[mi][1], a[mi][2], a[mi][3],
                             bb[ni][2], bb[ni][3]);
                }
        }
    }

    // ---- epilogue: D[m=o, n=p] + bias[o] -> out[b, c, t, p_base + ...]
    #pragma unroll
    for (int mi = 0; mi < 2; mi++) {
        #pragma unroll
        for (int rr = 0; rr < 2; rr++) {
            int o = o_base + warp_m * 32 + mi * 16 + rr * 8 + (lane >> 2);
            int s = o >> 5, c = o & 31;
            int t = ((g << 5) + s - 16) & 63;
            float bv = __ldg(&bias[o]);
            float* orow = out + (size_t)b * B_STRIDE + (size_t)c * CH_STRIDE
                        + t * HP3 + p_base + warp_n * 64 + 2 * (lane & 3);
            #pragma unroll
            for (int ni = 0; ni < 8; ni++) {
                float2 v;
                v.x = acc[mi][ni][rr * 2 + 0] + bv;
                v.y = acc[mi][ni][rr * 2 + 1] + bv;
                *reinterpret_cast<float2*>(orow + ni * 8) = v;
            }
        }
    }
}

// ---------------- launch ----------------
extern "C" void kernel_launch(void* const* d_in, const int* in_sizes, int n_in,
                              void* d_out, int out_size) {
    const float* x    = (const float*)d_in[0];   // (2,32,96,96,96) fp32
    const float* W    = (const float*)d_in[1];   // (1024,1024) fp32
    const float* bias = (const float*)d_in[2];   // (1024,) fp32
    float* out = (float*)d_out;

    cudaFuncSetAttribute(swin_gemm_kernel,
                         cudaFuncAttributeMaxDynamicSharedMemorySize, SMEM_BYTES);

    wconv_kernel<<<1024, 256>>>(W);

    dim3 grid(1024 / M_TILE, HP3 / N_TILE, 4);   // (8, 108, 4); x fastest -> X L2 reuse
    swin_gemm_kernel<<<grid, 256, SMEM_BYTES>>>(x, bias, out);
}

// round 10
// speedup vs baseline: 1.2104x; 1.2104x over previous
#include <cuda_runtime.h>
#include <cuda_fp16.h>
#include <cstdint>

// ============================================================================
// shift_Windows == 4 batched GEMMs:  Out[o,p] = sum_k W[o,k] * X[k,p] + bias[o]
//   per (b in {0,1}, g in {0,1}):  M(o)=1024, N(p)=13824, K=1024
//   X[k=s'*32+c', p] = x[b, c', t', p],  t' = (g*32 + s' - 16) & 63
//   Out row o=s*32+c  -> out[b, c, t, p], t = (g*32 + s - 16) & 63  (same map)
//
// Baseline compute_103 target: mma.sync.m16n8k16 + cp.async + ldmatrix.
// R9 = fused X conversion, occupancy fixed:
//   - B(X) read fp32 via LDG.128 at HALF-CHUNK granularity (16 live regs,
//     not 32), converted fp16, STS'd; LDG latency hidden under the MMA block.
//   - __launch_bounds__(256,2) forces <=128 regs -> 2 CTA/SM, 16 warps.
//   - A (W fp16 prepass) via cp.async, 3 stages (prefetch distance 2).
//   - One __syncthreads per K-chunk.
// ============================================================================

#define HP3        13824     // 24^3 spatial positions per (b, t)
#define CH_STRIDE  884736    // 64*13824  (channel stride in x/out, elements)
#define B_STRIDE   28311552  // 32*884736 (batch stride, elements)

#define M_TILE 128           // o rows per CTA
#define N_TILE 128           // p cols per CTA
#define N_CHUNKS 16          // 1024 / 64

#define OFF_A 0              // A = W tile: [128 o][64 k] fp16, 128B rows, x3 stages
#define OFF_B 49152          // B = X tile: [64 k][128 p] fp16, 256B rows, x2 buffers
#define SMEM_BYTES 81920     // 48KB A + 32KB B ; 2 CTAs = 160KB <= 227KB

__device__ __half d_Wh[1024 * 1024];      // fp16 W (prepass)

// ---------------- helpers ----------------
__device__ __forceinline__ uint32_t smem_to_u32(const void* p) {
    uint32_t a;
    asm("{ .reg .u64 t; cvta.to.shared.u64 t, %1; cvt.u32.u64 %0, t; }"
        : "=r"(a) : "l"(p));
    return a;
}
#define CP_ASYNC16(dst, src) \
    asm volatile("cp.async.cg.shared.global [%0], [%1], 16;" :: "r"(dst), "l"(src))
#define CP_COMMIT() asm volatile("cp.async.commit_group;" ::: "memory")
#define CP_WAIT(n)  asm volatile("cp.async.wait_group %0;" :: "n"(n) : "memory")

#define LDMATRIX_X4(r0, r1, r2, r3, addr) \
    asm volatile("ldmatrix.sync.aligned.m8n8.x4.shared.b16 {%0,%1,%2,%3}, [%4];" \
                 : "=r"(r0), "=r"(r1), "=r"(r2), "=r"(r3) : "r"(addr))
#define LDMATRIX_X4_T(r0, r1, r2, r3, addr) \
    asm volatile("ldmatrix.sync.aligned.m8n8.x4.trans.shared.b16 {%0,%1,%2,%3}, [%4];" \
                 : "=r"(r0), "=r"(r1), "=r"(r2), "=r"(r3) : "r"(addr))

#define MMA16816(d, a0, a1, a2, a3, b0, b1) \
    asm volatile("mma.sync.aligned.m16n8k16.row.col.f32.f16.f16.f32 " \
                 "{%0,%1,%2,%3}, {%4,%5,%6,%7}, {%8,%9}, {%0,%1,%2,%3};" \
                 : "+f"((d)[0]), "+f"((d)[1]), "+f"((d)[2]), "+f"((d)[3]) \
                 : "r"(a0), "r"(a1), "r"(a2), "r"(a3), "r"(b0), "r"(b1))

// ---------------- prepass: W fp32 -> fp16 ----------------
__global__ void __launch_bounds__(256) wconv_kernel(const float* __restrict__ W) {
    int i = blockIdx.x * 256 + threadIdx.x;        // 262144 float4's
    float4 v = ((const float4*)W)[i];
    __half2 a = __float22half2_rn(make_float2(v.x, v.y));
    __half2 c = __float22half2_rn(make_float2(v.z, v.w));
    uint2 u;
    u.x = *reinterpret_cast<const uint32_t*>(&a);
    u.y = *reinterpret_cast<const uint32_t*>(&c);
    ((uint2*)d_Wh)[i] = u;
}

// ---------------- main GEMM ----------------
__global__ void __launch_bounds__(256, 2)
swin_gemm_kernel(const float* __restrict__ x, const float* __restrict__ bias,
                 float* __restrict__ out) {
    extern __shared__ char sm[];
    const uint32_t smb = smem_to_u32(sm);
    const int tid  = threadIdx.x;
    const int lane = tid & 31;
    const int warp = tid >> 5;          // 0..7
    const int warp_m = warp & 3;        // o sub-tile (32 rows)
    const int warp_n = warp >> 2;       // p sub-tile (64 cols)

    const int o_base = blockIdx.x * M_TILE;
    const int p_base = blockIdx.y * N_TILE;
    const int bg = blockIdx.z;
    const int b  = bg >> 1;
    const int g  = bg & 1;

    float acc[2][8][4];
    #pragma unroll
    for (int mi = 0; mi < 2; mi++)
        #pragma unroll
        for (int ni = 0; ni < 8; ni++)
            #pragma unroll
            for (int r = 0; r < 4; r++) acc[mi][ni][r] = 0.f;

    // ---- A loader: W fp16 via cp.async, 3 stages (1024 x 16B chunks/stage)
    auto load_A = [&](int stage, int kc) {
        uint32_t abase = smb + OFF_A + stage * 16384;
        #pragma unroll
        for (int i = 0; i < 4; i++) {
            int cid = tid + i * 256;
            int o = cid >> 3, c16 = cid & 7;
            const __half* src = d_Wh + (size_t)(o_base + o) * 1024 + kc * 64 + c16 * 8;
            uint32_t dst = abase + o * 128 + ((c16 * 16) ^ ((o & 7) << 4));
            CP_ASYNC16(dst, src);
        }
    };

    // ---- B: X fp32 -> fp16, HALF-CHUNK granularity (4 float4 live regs)
    //   half h covers k rows 32h..32h+31 (cid = tid + (i+4h)*256, i<4)
    const float* xb = x + (size_t)b * B_STRIDE + p_base;
    float4 breg[4];

    auto ldg_half = [&](int kc, int h) {
        #pragma unroll
        for (int i = 0; i < 4; i++) {
            int cid = tid + (i + 4 * h) * 256;
            int kk = cid >> 5, c4 = cid & 31;
            int kg = kc * 64 + kk;
            int sp = kg >> 5, cp = kg & 31;
            int tp = ((g << 5) + sp - 16) & 63;
            breg[i] = *reinterpret_cast<const float4*>(
                xb + (size_t)cp * CH_STRIDE + (size_t)tp * HP3 + c4 * 4);
        }
    };
    auto cvt_half = [&](int buf, int h) {
        char* bbase = sm + OFF_B + buf * 16384;
        #pragma unroll
        for (int i = 0; i < 4; i++) {
            int cid = tid + (i + 4 * h) * 256;
            int kk = cid >> 5, c4 = cid & 31;
            float4 v = breg[i];
            __half2 h0 = __float22half2_rn(make_float2(v.x, v.y));
            __half2 h1 = __float22half2_rn(make_float2(v.z, v.w));
            uint2 u;
            u.x = *reinterpret_cast<const uint32_t*>(&h0);
            u.y = *reinterpret_cast<const uint32_t*>(&h1);
            uint32_t off = kk * 256 + ((((c4 >> 1) << 4) ^ ((kk & 7) << 4)))
                         + ((c4 & 1) << 3);
            *reinterpret_cast<uint2*>(bbase + off) = u;
        }
    };

    // ---- compute two k16 steps (one half of a chunk) ----
    auto compute_half = [&](uint32_t abase, uint32_t bbase, int h) {
        #pragma unroll
        for (int kq = 0; kq < 2; kq++) {
            const int k16 = 2 * h + kq;
            uint32_t a[2][4], bb[4][4];
            #pragma unroll
            for (int mi = 0; mi < 2; mi++) {
                int row = warp_m * 32 + mi * 16 + (lane & 15);
                int col = k16 * 32 + (lane >> 4) * 16;
                uint32_t addr = abase + row * 128 + (col ^ ((row & 7) << 4));
                LDMATRIX_X4(a[mi][0], a[mi][1], a[mi][2], a[mi][3], addr);
            }
            #pragma unroll
            for (int ni = 0; ni < 4; ni++) {
                int row = k16 * 16 + (lane & 15);
                int col = warp_n * 128 + ni * 32 + (lane >> 4) * 16;   // bytes
                uint32_t addr = bbase + row * 256 + (col ^ ((row & 7) << 4));
                LDMATRIX_X4_T(bb[ni][0], bb[ni][1], bb[ni][2], bb[ni][3], addr);
            }
            #pragma unroll
            for (int mi = 0; mi < 2; mi++)
                #pragma unroll
                for (int ni = 0; ni < 4; ni++) {
                    MMA16816(acc[mi][2 * ni],     a[mi][0], a[mi][1], a[mi][2], a[mi][3],
                             bb[ni][0], bb[ni][1]);
                    MMA16816(acc[mi][2 * ni + 1], a[mi][0], a[mi][1], a[mi][2], a[mi][3],
                             bb[ni][2], bb[ni][3]);
                }
        }
    };

    // ---- prologue: chunk 0 -> buf0 (no overlap available yet); A0, A1 in flight
    load_A(0, 0); CP_COMMIT();
    load_A(1, 1); CP_COMMIT();
    ldg_half(0, 0); cvt_half(0, 0);
    ldg_half(0, 1); cvt_half(0, 1);

    #pragma unroll 1
    for (int kc = 0; kc < N_CHUNKS; kc++) {
        const int buf = kc & 1;          // B read buffer
        const int astage = kc % 3;       // A read stage
        if (kc < N_CHUNKS - 1) { CP_WAIT(1); } else { CP_WAIT(0); }
        __syncthreads();   // A[kc] + B[kc] (stored prev iter / prologue) visible

        if (kc + 2 < N_CHUNKS) {
            load_A((kc + 2) % 3, kc + 2); CP_COMMIT();   // distinct stage: no alias
        }

        const uint32_t abase = smb + OFF_A + astage * 16384;
        const uint32_t bbase = smb + OFF_B + buf * 16384;
        const bool more = (kc + 1 < N_CHUNKS);

        // half 0: LDG next-chunk half0, MMA current half0 (hides LDG), cvt+STS
        if (more) ldg_half(kc + 1, 0);
        compute_half(abase, bbase, 0);
        if (more) cvt_half(buf ^ 1, 0);

        // half 1
        if (more) ldg_half(kc + 1, 1);
        compute_half(abase, bbase, 1);
        if (more) cvt_half(buf ^ 1, 1);
    }

    // ---- epilogue: D[m=o, n=p] + bias[o] -> out[b, c, t, p_base + ...]
    #pragma unroll
    for (int mi = 0; mi < 2; mi++) {
        #pragma unroll
        for (int rr = 0; rr < 2; rr++) {
            int o = o_base + warp_m * 32 + mi * 16 + rr * 8 + (lane >> 2);
            int s = o >> 5, c = o & 31;
            int t = ((g << 5) + s - 16) & 63;
            float bv = __ldg(&bias[o]);
            float* orow = out + (size_t)b * B_STRIDE + (size_t)c * CH_STRIDE
                        + t * HP3 + p_base + warp_n * 64 + 2 * (lane & 3);
            #pragma unroll
            for (int ni = 0; ni < 8; ni++) {
                float2 v;
                v.x = acc[mi][ni][rr * 2 + 0] + bv;
                v.y = acc[mi][ni][rr * 2 + 1] + bv;
                *reinterpret_cast<float2*>(orow + ni * 8) = v;
            }
        }
    }
}

// ---------------- launch ----------------
extern "C" void kernel_launch(void* const* d_in, const int* in_sizes, int n_in,
                              void* d_out, int out_size) {
    const float* x    = (const float*)d_in[0];   // (2,32,96,96,96) fp32
    const float* W    = (const float*)d_in[1];   // (1024,1024) fp32
    const float* bias = (const float*)d_in[2];   // (1024,) fp32
    float* out = (float*)d_out;

    cudaFuncSetAttribute(swin_gemm_kernel,
                         cudaFuncAttributeMaxDynamicSharedMemorySize, SMEM_BYTES);

    wconv_kernel<<<1024, 256>>>(W);

    dim3 grid(1024 / M_TILE, HP3 / N_TILE, 4);   // (8, 108, 4); x fastest -> X L2 reuse
    swin_gemm_kernel<<<grid, 256, SMEM_BYTES>>>(x, bias, out);
}

// round 11
// speedup vs baseline: 1.2529x; 1.0351x over previous
#include <cuda_runtime.h>
#include <cuda_fp16.h>
#include <cstdint>

// ============================================================================
// shift_Windows == 4 batched GEMMs:  Out[o,p] = sum_k W[o,k] * X[k,p] + bias[o]
//   per (b in {0,1}, g in {0,1}):  M(o)=1024, N(p)=13824, K=1024
//   X[k=s'*32+c', p] = x[b, c', t', p],  t' = (g*32 + s' - 16) & 63
//   Out row o=s*32+c  -> out[b, c, t, p], t = (g*32 + s - 16) & 63  (same map)
//
// Baseline compute_103 target: mma.sync.m16n8k16 + cp.async + ldmatrix.
// R10: GEMM is smem-crossbar-bound (128B/cyc/SM). Revert to the minimal
// crossbar-traffic structure (R3: both operands fp16 via cp.async, 128KB per
// CTA-chunk) and add only crossbar-neutral wins:
//   - 3-stage pipeline, ONE __syncthreads per K-chunk (was 2-stage/2-sync)
//   - wconv+xconv fused into a single prepass launch
//   - streaming (__stcs) epilogue stores: keep write-once 'out' out of L2
// ============================================================================

#define HP3        13824     // 24^3 spatial positions per (b, t)
#define CH_STRIDE  884736    // 64*13824  (channel stride in x/out, elements)
#define B_STRIDE   28311552  // 32*884736 (batch stride, elements)

#define M_TILE 128           // o rows per CTA
#define N_TILE 128           // p cols per CTA
#define N_CHUNKS 16          // 1024 / 64

#define STAGE_BYTES 32768    // A 16KB + B 16KB
#define OFF_B_IN_STAGE 16384
#define SMEM_BYTES (3 * STAGE_BYTES)   // 96KB; 2 CTAs = 192KB <= 227KB

__device__ __half d_Wh[1024 * 1024];      // fp16 W
__device__ __half d_Xh[56623104];         // fp16 x  (2*32*96^3)

// ---------------- helpers ----------------
__device__ __forceinline__ uint32_t smem_to_u32(const void* p) {
    uint32_t a;
    asm("{ .reg .u64 t; cvta.to.shared.u64 t, %1; cvt.u32.u64 %0, t; }"
        : "=r"(a) : "l"(p));
    return a;
}
#define CP_ASYNC16(dst, src) \
    asm volatile("cp.async.cg.shared.global [%0], [%1], 16;" :: "r"(dst), "l"(src))
#define CP_COMMIT() asm volatile("cp.async.commit_group;" ::: "memory")
#define CP_WAIT(n)  asm volatile("cp.async.wait_group %0;" :: "n"(n) : "memory")

#define LDMATRIX_X4(r0, r1, r2, r3, addr) \
    asm volatile("ldmatrix.sync.aligned.m8n8.x4.shared.b16 {%0,%1,%2,%3}, [%4];" \
                 : "=r"(r0), "=r"(r1), "=r"(r2), "=r"(r3) : "r"(addr))
#define LDMATRIX_X4_T(r0, r1, r2, r3, addr) \
    asm volatile("ldmatrix.sync.aligned.m8n8.x4.trans.shared.b16 {%0,%1,%2,%3}, [%4];" \
                 : "=r"(r0), "=r"(r1), "=r"(r2), "=r"(r3) : "r"(addr))

#define MMA16816(d, a0, a1, a2, a3, b0, b1) \
    asm volatile("mma.sync.aligned.m16n8k16.row.col.f32.f16.f16.f32 " \
                 "{%0,%1,%2,%3}, {%4,%5,%6,%7}, {%8,%9}, {%0,%1,%2,%3};" \
                 : "+f"((d)[0]), "+f"((d)[1]), "+f"((d)[2]), "+f"((d)[3]) \
                 : "r"(a0), "r"(a1), "r"(a2), "r"(a3), "r"(b0), "r"(b1))

// ---------------- fused prepass: W and X fp32 -> fp16 (one launch) ----------
// blocks [0, 1024)           : W   (262144 float4)
// blocks [1024, 1024+55296)  : X   (14155776 float4)
__global__ void __launch_bounds__(256) conv_kernel(const float* __restrict__ W,
                                                   const float* __restrict__ x) {
    const float* src;
    uint2* dst;
    int i;
    if (blockIdx.x < 1024) {
        i = blockIdx.x * 256 + threadIdx.x;
        src = W; dst = (uint2*)d_Wh;
    } else {
        i = (blockIdx.x - 1024) * 256 + threadIdx.x;
        src = x; dst = (uint2*)d_Xh;
    }
    float4 v = ((const float4*)src)[i];
    __half2 a = __float22half2_rn(make_float2(v.x, v.y));
    __half2 c = __float22half2_rn(make_float2(v.z, v.w));
    uint2 u;
    u.x = *reinterpret_cast<const uint32_t*>(&a);
    u.y = *reinterpret_cast<const uint32_t*>(&c);
    dst[i] = u;
}

// ---------------- main GEMM ----------------
__global__ void __launch_bounds__(256, 2)
swin_gemm_kernel(const float* __restrict__ bias, float* __restrict__ out) {
    extern __shared__ char sm[];
    const uint32_t smb = smem_to_u32(sm);
    const int tid  = threadIdx.x;
    const int lane = tid & 31;
    const int warp = tid >> 5;          // 0..7
    const int warp_m = warp & 3;        // o sub-tile (32 rows)
    const int warp_n = warp >> 2;       // p sub-tile (64 cols)

    const int o_base = blockIdx.x * M_TILE;
    const int p_base = blockIdx.y * N_TILE;
    const int bg = blockIdx.z;
    const int b  = bg >> 1;
    const int g  = bg & 1;

    float acc[2][8][4];
    #pragma unroll
    for (int mi = 0; mi < 2; mi++)
        #pragma unroll
        for (int ni = 0; ni < 8; ni++)
            #pragma unroll
            for (int r = 0; r < 4; r++) acc[mi][ni][r] = 0.f;

    // ---- tile loaders (cp.async, both fp16, contiguous 16B chunks) ----
    auto load_tiles = [&](int stage, int kc) {
        // A = W[o_base..+128][kc*64..+64], rows 128B, swizzled  (1024 chunks)
        uint32_t abase = smb + stage * STAGE_BYTES;
        #pragma unroll
        for (int i = 0; i < 4; i++) {
            int cid = tid + i * 256;
            int o = cid >> 3, c16 = cid & 7;
            const __half* src = d_Wh + (size_t)(o_base + o) * 1024 + kc * 64 + c16 * 8;
            uint32_t dst = abase + o * 128 + ((c16 * 16) ^ ((o & 7) << 4));
            CP_ASYNC16(dst, src);
        }
        // B = X[kc*64..+64][p_base..+128], rows 256B, swizzled by (k&7)  (1024 chunks)
        uint32_t bbase = abase + OFF_B_IN_STAGE;
        #pragma unroll
        for (int i = 0; i < 4; i++) {
            int cid = tid + i * 256;
            int kk = cid >> 4, c16 = cid & 15;
            int kg = kc * 64 + kk;
            int sp = kg >> 5, cp = kg & 31;
            int tp = ((g << 5) + sp - 16) & 63;
            const __half* src = d_Xh + (size_t)b * B_STRIDE + (size_t)cp * CH_STRIDE
                              + tp * HP3 + p_base + c16 * 8;
            uint32_t dst = bbase + kk * 256 + ((c16 * 16) ^ ((kk & 7) << 4));
            CP_ASYNC16(dst, src);
        }
    };

    load_tiles(0, 0); CP_COMMIT();
    load_tiles(1, 1); CP_COMMIT();

    #pragma unroll 1
    for (int kc = 0; kc < N_CHUNKS; kc++) {
        const int stage = kc % 3;
        if (kc < N_CHUNKS - 1) { CP_WAIT(1); } else { CP_WAIT(0); }
        __syncthreads();   // stage[kc] data visible to all; stage (kc+2)%3 free
        if (kc + 2 < N_CHUNKS) {
            load_tiles((kc + 2) % 3, kc + 2);
            CP_COMMIT();
        }

        const uint32_t abase = smb + stage * STAGE_BYTES;
        const uint32_t bbase = abase + OFF_B_IN_STAGE;
        #pragma unroll
        for (int k16 = 0; k16 < 4; k16++) {
            uint32_t a[2][4], bb[4][4];
            #pragma unroll
            for (int mi = 0; mi < 2; mi++) {
                int row = warp_m * 32 + mi * 16 + (lane & 15);
                int col = k16 * 32 + (lane >> 4) * 16;
                uint32_t addr = abase + row * 128 + (col ^ ((row & 7) << 4));
                LDMATRIX_X4(a[mi][0], a[mi][1], a[mi][2], a[mi][3], addr);
            }
            #pragma unroll
            for (int ni = 0; ni < 4; ni++) {
                int row = k16 * 16 + (lane & 15);
                int col = warp_n * 128 + ni * 32 + (lane >> 4) * 16;   // bytes
                uint32_t addr = bbase + row * 256 + (col ^ ((row & 7) << 4));
                LDMATRIX_X4_T(bb[ni][0], bb[ni][1], bb[ni][2], bb[ni][3], addr);
            }
            #pragma unroll
            for (int mi = 0; mi < 2; mi++)
                #pragma unroll
                for (int ni = 0; ni < 4; ni++) {
                    MMA16816(acc[mi][2 * ni],     a[mi][0], a[mi][1], a[mi][2], a[mi][3],
                             bb[ni][0], bb[ni][1]);
                    MMA16816(acc[mi][2 * ni + 1], a[mi][0], a[mi][1], a[mi][2], a[mi][3],
                             bb[ni][2], bb[ni][3]);
                }
        }
    }

    // ---- epilogue: D[m=o, n=p] + bias[o] -> out[b, c, t, ...], streaming stores
    #pragma unroll
    for (int mi = 0; mi < 2; mi++) {
        #pragma unroll
        for (int rr = 0; rr < 2; rr++) {
            int o = o_base + warp_m * 32 + mi * 16 + rr * 8 + (lane >> 2);
            int s = o >> 5, c = o & 31;
            int t = ((g << 5) + s - 16) & 63;
            float bv = __ldg(&bias[o]);
            float* orow = out + (size_t)b * B_STRIDE + (size_t)c * CH_STRIDE
                        + t * HP3 + p_base + warp_n * 64 + 2 * (lane & 3);
            #pragma unroll
            for (int ni = 0; ni < 8; ni++) {
                float2 v;
                v.x = acc[mi][ni][rr * 2 + 0] + bv;
                v.y = acc[mi][ni][rr * 2 + 1] + bv;
                __stcs(reinterpret_cast<float2*>(orow + ni * 8), v);
            }
        }
    }
}

// ---------------- launch ----------------
extern "C" void kernel_launch(void* const* d_in, const int* in_sizes, int n_in,
                              void* d_out, int out_size) {
    const float* x    = (const float*)d_in[0];   // (2,32,96,96,96) fp32
    const float* W    = (const float*)d_in[1];   // (1024,1024) fp32
    const float* bias = (const float*)d_in[2];   // (1024,) fp32
    float* out = (float*)d_out;

    cudaFuncSetAttribute(swin_gemm_kernel,
                         cudaFuncAttributeMaxDynamicSharedMemorySize, SMEM_BYTES);

    conv_kernel<<<1024 + 55296, 256>>>(W, x);    // fused W+X fp32->fp16

    dim3 grid(1024 / M_TILE, HP3 / N_TILE, 4);   // (8, 108, 4); x fastest -> X L2 reuse
    swin_gemm_kernel<<<grid, 256, SMEM_BYTES>>>(bias, out);
}